// round 6
// baseline (speedup 1.0000x reference)
#include <cuda_runtime.h>
#include <math.h>
#include <math_constants.h>

#define NPIX 768
#define NB   32
#define PATCH 128
#define NT   64          // 8x8 patches per image
#define TM   128         // matmul tile
#define KC   8           // matmul k-chunk
#define RS   8           // corr_rigid row-stripe

// ---------------- scratch (static device globals; no runtime alloc) -------
__device__ float  g_cr[NB][121];              // rigid corr window (SIGNED partial sums)
__device__ float  g_S[NB];                    // checkerboard sum per image
__device__ float  g_rsh[NB][2];               // rigid shifts (shx, shy)
__device__ float  g_hr[NB][2][NPIX];          // REAL fractional-shift kernels
__device__ float  g_sig[NB];                  // sin(pi s1) sin(pi s2) / N^2
__device__ float  g_ur[(size_t)NB*NPIX*NPIX]; // pass1 result (real)
__device__ float  g_pncc[NB*NT][121];         // patch ncc windows (abs)
__device__ float  g_sx[NB*NT];                // shift_img_x flattened
__device__ float  g_sy[NB*NT];                // shift_img_y flattened

// ---------------- helpers -------------------------------------------------
__device__ __forceinline__ float lgclip(const float* ncc, int a, int b) {
    a = a < 0 ? 0 : (a > 10 ? 10 : a);
    b = b < 0 ? 0 : (b > 10 ? 10 : b);
    return logf(ncc[a * 11 + b] + 1e-8f);
}

__device__ __forceinline__ void subpixel11(const float* ncc, float lbx, float lby,
                                           float* oshx, float* oshy) {
    int am = 0; float best = ncc[0];
    #pragma unroll 1
    for (int i = 1; i < 121; i++) { if (ncc[i] > best) { best = ncc[i]; am = i; } }
    int sx = am / 11, sy = am % 11;
    float lxm = lgclip(ncc, sx - 1, sy);
    float lxp = lgclip(ncc, sx + 1, sy);
    float lym = lgclip(ncc, sx, sy - 1);
    float lyp = lgclip(ncc, sx, sy + 1);
    float l0  = 4.0f * lgclip(ncc, sx, sy);
    *oshx = -((float)sx + lbx) - (lxm - lxp) / (2.0f * lxm - l0 + 2.0f * lxp);
    *oshy = -((float)sy + lby) - (lym - lyp) / (2.0f * lym - l0 + 2.0f * lyp);
}

// ---------------- stage 0: zero accumulators ------------------------------
__global__ void init_zero() {
    int i = blockIdx.x * 256 + threadIdx.x;
    if (i < NB * 121) ((float*)g_cr)[i] = 0.f;
    if (i < NB) g_S[i] = 0.f;
}

// ---------------- stage 0b: checkerboard sum S_b = sum (-1)^{m+n} D ------
__global__ void sum_sign(const float* __restrict__ data) {
    int b = blockIdx.y;
    const float* D = data + (size_t)b * NPIX * NPIX;
    float acc = 0.f;
    for (int i = blockIdx.x * 256 + threadIdx.x; i < NPIX * NPIX; i += gridDim.x * 256) {
        float v = D[i];
        // NPIX even -> n parity == i parity; sign = (-1)^{m+n}
        int par = ((i / NPIX) + i) & 1;
        acc += par ? -v : v;
    }
    acc += __shfl_down_sync(0xffffffffu, acc, 16);
    acc += __shfl_down_sync(0xffffffffu, acc, 8);
    acc += __shfl_down_sync(0xffffffffu, acc, 4);
    acc += __shfl_down_sync(0xffffffffu, acc, 2);
    acc += __shfl_down_sync(0xffffffffu, acc, 1);
    __shared__ float sw[8];
    int lane = threadIdx.x & 31, wrp = threadIdx.x >> 5;
    if (lane == 0) sw[wrp] = acc;
    __syncthreads();
    if (threadIdx.x == 0) {
        float s = 0.f;
        #pragma unroll
        for (int w = 0; w < 8; w++) s += sw[w];
        atomicAdd(&g_S[b], s);
    }
}

// ---------------- stage A: rigid correlation (row-stripe blocks) ----------
// c[a,b] = sum_{x,y} data[x,y] * tpl[(x-a)%N, (y-b)%N],  a,b in [-5,5]
__global__ __launch_bounds__(256) void corr_rigid(const float* __restrict__ data,
                                                  const float* __restrict__ tpl) {
    extern __shared__ float sm2[];
    float* sdat = sm2;                 // RS * NPIX
    float* stpl = sm2 + RS * NPIX;     // (RS+10) * NPIX
    int b = blockIdx.y, X0 = blockIdx.x * RS;
    int tid = threadIdx.x;
    const float* D = data + (size_t)b * NPIX * NPIX + (size_t)X0 * NPIX;

    for (int i = tid; i < RS * NPIX / 4; i += 256)
        ((float4*)sdat)[i] = ((const float4*)D)[i];
    for (int i = tid; i < (RS + 10) * NPIX / 4; i += 256) {
        int r = i / (NPIX / 4), c4 = i % (NPIX / 4);
        int gr = X0 - 5 + r;
        if (gr < 0) gr += NPIX; else if (gr >= NPIX) gr -= NPIX;
        ((float4*)stpl)[i] = ((const float4*)(tpl + (size_t)gr * NPIX))[c4];
    }
    __syncthreads();

    __shared__ float swr[8][11];
    int lane = tid & 31, wrp = tid >> 5;
    for (int wi = 0; wi < 11; wi++) {
        float acc[11];
        #pragma unroll
        for (int j = 0; j < 11; j++) acc[j] = 0.f;
        #pragma unroll 1
        for (int g = 0; g < 6; g++) {
            int gid = tid + g * 256;          // 0..1535 = 8 rows * 192 groups
            int x = gid / 192;
            int y0 = (gid % 192) * 4;
            float4 p4 = *(const float4*)&sdat[x * NPIX + y0];
            const float* rp = stpl + (x + 10 - wi) * NPIX;
            int ysc = y0 - 5;  if (ysc < 0) ysc += NPIX;
            int ym  = y0 - 4;  if (ym  < 0) ym  += NPIX;
            int yp1 = y0 + 4;  if (yp1 >= NPIX) yp1 -= NPIX;
            int yp2 = y0 + 8;  if (yp2 >= NPIX) yp2 -= NPIX;
            float4 Bq = *(const float4*)&rp[ym];
            float4 Cq = *(const float4*)&rp[y0];
            float4 Dq = *(const float4*)&rp[yp1];
            float tv[14] = { rp[ysc], Bq.x, Bq.y, Bq.z, Bq.w,
                             Cq.x, Cq.y, Cq.z, Cq.w, Dq.x, Dq.y, Dq.z, Dq.w, rp[yp2] };
            float pv[4] = { p4.x, p4.y, p4.z, p4.w };
            #pragma unroll
            for (int wj = 0; wj < 11; wj++)
                #pragma unroll
                for (int yo = 0; yo < 4; yo++)
                    acc[wj] += pv[yo] * tv[yo + 10 - wj];
        }
        #pragma unroll
        for (int j = 0; j < 11; j++) {
            float v = acc[j];
            v += __shfl_down_sync(0xffffffffu, v, 16);
            v += __shfl_down_sync(0xffffffffu, v, 8);
            v += __shfl_down_sync(0xffffffffu, v, 4);
            v += __shfl_down_sync(0xffffffffu, v, 2);
            v += __shfl_down_sync(0xffffffffu, v, 1);
            if (lane == 0) swr[wrp][j] = v;
        }
        __syncthreads();
        if (tid < 11) {
            float s = 0.f;
            #pragma unroll
            for (int w = 0; w < 8; w++) s += swr[w][tid];
            atomicAdd(&g_cr[b][wi * 11 + tid], s);
        }
        __syncthreads();
    }
}

// ---------------- stage A2: rigid subpixel (fabs of accumulated sums) -----
__global__ void rigid_subpixel(float* __restrict__ out_rs) {
    int b = threadIdx.x;
    if (b >= NB) return;
    float loc[121];
    for (int i = 0; i < 121; i++) loc[i] = fabsf(g_cr[b][i]);
    float shx, shy;
    subpixel11(loc, -5.0f, -5.0f, &shx, &shy);
    g_rsh[b][0] = shx; g_rsh[b][1] = shy;
    out_rs[b * 2 + 0] = shx;
    out_rs[b * 2 + 1] = shy;
}

// ---------------- stage B0: real Dirichlet shift kernels ------------------
__global__ void compute_h() {
    int b = blockIdx.x, axis = blockIdx.y, j = threadIdx.x;
    double s = (double)g_rsh[b][axis];
    double t = (double)j - s;
    double a = CUDART_PI * t / 768.0;
    double S1r, S1i;
    double den = sin(a);
    if (fabs(den) < 1e-12) { S1r = 384.0; S1i = 0.0; }
    else {
        double ratio = sin(384.0 * a) / den;
        double ph = 383.0 * a;
        S1r = ratio * cos(ph); S1i = ratio * sin(ph);
    }
    double ang = 2.0 * CUDART_PI * s + CUDART_PI * t;
    double fr = 1.0 + cos(ang), fi = sin(ang);
    g_hr[b][axis][j] = (float)((S1r * fr - S1i * fi) / 768.0);
    if (j == 0 && axis == 0) {
        double s1 = (double)g_rsh[b][0], s2 = (double)g_rsh[b][1];
        g_sig[b] = (float)(sin(CUDART_PI * s1) * sin(CUDART_PI * s2) / (768.0 * 768.0));
    }
}

// ---------------- stage B1: u = R1 * D (real circulant matmul) ------------
__global__ __launch_bounds__(256) void pass1(const float* __restrict__ data) {
    int x0 = blockIdx.y * TM, y0 = blockIdx.x * TM, b = blockIdx.z;
    const float* D = data + (size_t)b * NPIX * NPIX;
    const float* h = g_hr[b][0];
    __shared__ float sd[KC][TM];
    __shared__ float sh[TM + KC];
    int tx = threadIdx.x, ty = threadIdx.y, tid = ty * 16 + tx;
    float acc[8][8];
    #pragma unroll
    for (int i = 0; i < 8; i++)
        #pragma unroll
        for (int j = 0; j < 8; j++) acc[i][j] = 0.f;

    for (int m0 = 0; m0 < NPIX; m0 += KC) {
        {
            int idx = tid * 4;
            int mm = idx >> 7, yy = idx & 127;
            *(float4*)&sd[mm][yy] = *(const float4*)&D[(size_t)(m0 + mm) * NPIX + y0 + yy];
        }
        if (tid < TM + KC - 1) {
            int hj = x0 - m0 - (KC - 1) + tid;
            if (hj < 0) hj += NPIX; else if (hj >= NPIX) hj -= NPIX;
            sh[tid] = h[hj];
        }
        __syncthreads();
        float tv[15];
        #pragma unroll
        for (int q = 0; q < 15; q++) tv[q] = sh[ty * 8 + q];
        #pragma unroll
        for (int mm = 0; mm < KC; mm++) {
            float dv[8];
            *(float4*)&dv[0] = *(const float4*)&sd[mm][tx * 8];
            *(float4*)&dv[4] = *(const float4*)&sd[mm][tx * 8 + 4];
            #pragma unroll
            for (int i = 0; i < 8; i++) {
                float hv = tv[i + (KC - 1) - mm];
                #pragma unroll
                for (int j = 0; j < 8; j++) acc[i][j] += hv * dv[j];
            }
        }
        __syncthreads();
    }
    float* ur = g_ur + (size_t)b * NPIX * NPIX;
    #pragma unroll
    for (int i = 0; i < 8; i++) {
        int x = x0 + ty * 8 + i;
        *(float4*)&ur[(size_t)x * NPIX + y0 + tx * 8]     = *(float4*)&acc[i][0];
        *(float4*)&ur[(size_t)x * NPIX + y0 + tx * 8 + 4] = *(float4*)&acc[i][4];
    }
}

// ---------------- stage B2: out = u * R2^T - alpha * v v^T ----------------
__global__ __launch_bounds__(256) void pass2(float* __restrict__ out) {
    int x0 = blockIdx.y * TM, y0 = blockIdx.x * TM, b = blockIdx.z;
    const float* u = g_ur + (size_t)b * NPIX * NPIX;
    const float* h = g_hr[b][1];
    __shared__ float su[TM][KC + 1];
    __shared__ float sh[TM + KC];
    int tx = threadIdx.x, ty = threadIdx.y, tid = ty * 16 + tx;
    float acc[8][8];
    #pragma unroll
    for (int i = 0; i < 8; i++)
        #pragma unroll
        for (int j = 0; j < 8; j++) acc[i][j] = 0.f;

    for (int m0 = 0; m0 < NPIX; m0 += KC) {
        {
            int xx = tid >> 1, half = tid & 1;
            float4 v = *(const float4*)&u[(size_t)(x0 + xx) * NPIX + m0 + half * 4];
            su[xx][half * 4 + 0] = v.x; su[xx][half * 4 + 1] = v.y;
            su[xx][half * 4 + 2] = v.z; su[xx][half * 4 + 3] = v.w;
        }
        if (tid < TM + KC - 1) {
            int hj = y0 - m0 - (KC - 1) + tid;
            if (hj < 0) hj += NPIX; else if (hj >= NPIX) hj -= NPIX;
            sh[tid] = h[hj];
        }
        __syncthreads();
        float tv[15];
        #pragma unroll
        for (int q = 0; q < 15; q++) tv[q] = sh[tx * 8 + q];
        #pragma unroll
        for (int mm = 0; mm < KC; mm++) {
            float uv[8];
            #pragma unroll
            for (int i = 0; i < 8; i++) uv[i] = su[ty * 8 + i][mm];
            #pragma unroll
            for (int i = 0; i < 8; i++)
                #pragma unroll
                for (int j = 0; j < 8; j++)
                    acc[i][j] += uv[i] * tv[j + (KC - 1) - mm];
        }
        __syncthreads();
    }
    float alpha = g_sig[b] * g_S[b];
    float* O = out + (size_t)b * NPIX * NPIX;
    #pragma unroll
    for (int i = 0; i < 8; i++) {
        int x = x0 + ty * 8 + i;
        #pragma unroll
        for (int j = 0; j < 8; j++) {
            int y = y0 + tx * 8 + j;
            float corr = ((x + y) & 1) ? -alpha : alpha;   // alpha * (-1)^{x+y}
            acc[i][j] -= corr;
        }
        *(float4*)&O[(size_t)x * NPIX + y0 + tx * 8]     = *(float4*)&acc[i][0];
        *(float4*)&O[(size_t)x * NPIX + y0 + tx * 8 + 4] = *(float4*)&acc[i][4];
    }
}

// ---------------- stage C: patchwise correlation windows ------------------
__global__ __launch_bounds__(256) void patch_corr(const float* __restrict__ data,
                                                  const float* __restrict__ tpl) {
    int p = blockIdx.x;
    int b = p >> 6, t = p & 63;
    int ix = t >> 3, iy = t & 7;
    int xs = (ix < 7) ? 96 * ix : 640;
    int ys = (iy < 7) ? 96 * iy : 640;
    extern __shared__ float sm[];
    float* spat = sm;
    float* stpl = sm + PATCH * PATCH;
    int tid = threadIdx.x;
    const float* D = data + (size_t)b * NPIX * NPIX;

    float rshx = g_rsh[b][0], rshy = g_rsh[b][1];
    int lbx = (int)floorf(-rshx - 5.0f);
    int lby = (int)floorf(-rshy - 5.0f);
    int stx = min(max(64 + lbx, 0), 117);
    int sty = min(max(64 + lby, 0), 117);
    int rot = (54 - sty) & 127;       // pre-rotate template columns

    for (int i = tid; i < PATCH * PATCH; i += 256) {
        int x = i >> 7, y = i & 127;
        spat[i] = D[(size_t)(xs + x) * NPIX + ys + y];
        stpl[i] = tpl[(size_t)(xs + x) * NPIX + ys + ((y + rot) & 127)];
    }
    __syncthreads();

    __shared__ float swr[8][11];
    int lane = tid & 31, wrp = tid >> 5;
    for (int wi = 0; wi < 11; wi++) {
        int a = stx + wi - 64;
        float acc[11];
        #pragma unroll
        for (int j = 0; j < 11; j++) acc[j] = 0.f;
        #pragma unroll 1
        for (int g4 = tid; g4 < 4096; g4 += 256) {
            int x  = g4 >> 5;
            int y0 = (g4 & 31) << 2;
            int txr = ((x - a) + 128) & 127;
            const float* row = stpl + txr * 128;
            const float4 p4 = *reinterpret_cast<const float4*>(spat + x * 128 + y0);
            int y1 = (y0 + 4) & 127, y2 = (y0 + 8) & 127;
            float4 A = *(const float4*)&row[y0];
            float4 Bq = *(const float4*)&row[y1];
            float4 Cq = *(const float4*)&row[y2];
            float tv[14] = { A.x, A.y, A.z, A.w, Bq.x, Bq.y, Bq.z, Bq.w,
                             Cq.x, Cq.y, Cq.z, Cq.w,
                             row[(y0 + 12) & 127], row[(y0 + 13) & 127] };
            float pv[4] = { p4.x, p4.y, p4.z, p4.w };
            #pragma unroll
            for (int wj = 0; wj < 11; wj++)
                #pragma unroll
                for (int yo = 0; yo < 4; yo++)
                    acc[wj] += pv[yo] * tv[yo + 10 - wj];
        }
        #pragma unroll
        for (int wj = 0; wj < 11; wj++) {
            float v = acc[wj];
            v += __shfl_down_sync(0xffffffffu, v, 16);
            v += __shfl_down_sync(0xffffffffu, v, 8);
            v += __shfl_down_sync(0xffffffffu, v, 4);
            v += __shfl_down_sync(0xffffffffu, v, 2);
            v += __shfl_down_sync(0xffffffffu, v, 1);
            if (lane == 0) swr[wrp][wj] = v;
        }
        __syncthreads();
        if (tid < 11) {
            float s = 0.f;
            #pragma unroll
            for (int w = 0; w < 8; w++) s += swr[w][tid];
            g_pncc[p][wi * 11 + tid] = fabsf(s);
        }
        __syncthreads();
    }
}

// ---------------- stage D: patch subpixel ---------------------------------
__global__ void patch_subpixel(float* __restrict__ out_sx, float* __restrict__ out_sy) {
    int p = blockIdx.x * blockDim.x + threadIdx.x;
    if (p >= NB * NT) return;
    int b = p >> 6;
    float rshx = g_rsh[b][0], rshy = g_rsh[b][1];
    float lbx = floorf(-rshx - 5.0f);
    float lby = floorf(-rshy - 5.0f);
    float shx, shy;
    subpixel11(g_pncc[p], lbx, lby, &shx, &shy);
    out_sx[p] = -shx; g_sx[p] = -shx;
    out_sy[p] = -shy; g_sy[p] = -shy;
}

// ---------------- stage E+F: upsample shift fields + warp -----------------
__device__ __forceinline__ float sample0(const float* D, int xi, int yi) {
    bool v = (xi >= 0) & (xi < NPIX) & (yi >= 0) & (yi < NPIX);
    int xc = min(max(xi, 0), NPIX - 1);
    int yc = min(max(yi, 0), NPIX - 1);
    float val = D[yc * NPIX + xc];
    return v ? val : 0.0f;
}

__global__ void warp_pw(const float* __restrict__ data, float* __restrict__ out) {
    int lin = blockIdx.x * 256 + threadIdx.x;
    if (lin >= NPIX * NPIX) return;
    int b = blockIdx.y;
    int X = lin / NPIX, Y = lin % NPIX;
    float fi = (X + 0.5f) * (1.0f / 96.0f) - 0.5f;
    float fj = (Y + 0.5f) * (1.0f / 96.0f) - 0.5f;
    float fi0 = floorf(fi), fj0 = floorf(fj);
    float ti = fi - fi0, tj = fj - fj0;
    int i0 = (int)fi0, j0 = (int)fj0;
    int ia = min(max(i0, 0), 7),     ib = min(max(i0 + 1, 0), 7);
    int ja = min(max(j0, 0), 7),     jb = min(max(j0 + 1, 0), 7);
    const float* sxp = g_sx + b * 64;
    const float* syp = g_sy + b * 64;
    float w00 = (1 - ti) * (1 - tj), w01 = (1 - ti) * tj;
    float w10 = ti * (1 - tj),       w11v = ti * tj;
    float sxv = sxp[ia * 8 + ja] * w00 + sxp[ia * 8 + jb] * w01
              + sxp[ib * 8 + ja] * w10 + sxp[ib * 8 + jb] * w11v;
    float syv = syp[ia * 8 + ja] * w00 + syp[ia * 8 + jb] * w01
              + syp[ib * 8 + ja] * w10 + syp[ib * 8 + jb] * w11v;
    float wx = syv + (float)Y;
    float wy = sxv + (float)X;
    float x0f = floorf(wx), y0f = floorf(wy);
    float dx = wx - x0f, dy = wy - y0f;
    int x0 = (int)x0f, y0 = (int)y0f;
    const float* D = data + (size_t)b * NPIX * NPIX;
    float r = sample0(D, x0, y0)         * (1 - dx) * (1 - dy)
            + sample0(D, x0 + 1, y0)     * dx * (1 - dy)
            + sample0(D, x0, y0 + 1)     * (1 - dx) * dy
            + sample0(D, x0 + 1, y0 + 1) * dx * dy;
    out[(size_t)b * NPIX * NPIX + lin] = r;
}

// ---------------- launch --------------------------------------------------
extern "C" void kernel_launch(void* const* d_in, const int* in_sizes, int n_in,
                              void* d_out, int out_size) {
    const float* data = (const float*)d_in[0];
    const float* tpl  = (const float*)d_in[1];
    if (n_in >= 2 && in_sizes[0] == NPIX * NPIX && in_sizes[1] != NPIX * NPIX) {
        const float* t2 = data; data = tpl; tpl = t2;
    }
    float* out = (float*)d_out;
    const size_t IMG = (size_t)NPIX * NPIX;
    float* out_pw    = out;
    float* out_rigid = out + NB * IMG;
    float* out_rs    = out + 2 * NB * IMG;
    float* out_sx    = out_rs + NB * 2;
    float* out_sy    = out_sx + NB * NT;

    init_zero<<<16, 256>>>();
    sum_sign<<<dim3(32, NB), 256>>>(data);

    int crSmem = (RS + RS + 10) * NPIX * (int)sizeof(float);   // 26*768*4 = 79872
    cudaFuncSetAttribute(corr_rigid, cudaFuncAttributeMaxDynamicSharedMemorySize, crSmem);
    corr_rigid<<<dim3(NPIX / RS, NB), 256, crSmem>>>(data, tpl);

    rigid_subpixel<<<1, 32>>>(out_rs);
    compute_h<<<dim3(NB, 2), NPIX>>>();

    pass1<<<dim3(6, 6, NB), dim3(16, 16)>>>(data);
    pass2<<<dim3(6, 6, NB), dim3(16, 16)>>>(out_rigid);

    int pcSmem = 2 * PATCH * PATCH * (int)sizeof(float);
    cudaFuncSetAttribute(patch_corr, cudaFuncAttributeMaxDynamicSharedMemorySize, pcSmem);
    patch_corr<<<NB * NT, 256, pcSmem>>>(data, tpl);

    patch_subpixel<<<(NB * NT + 255) / 256, 256>>>(out_sx, out_sy);
    warp_pw<<<dim3((NPIX * NPIX + 255) / 256, NB), 256>>>(data, out_pw);
}

// round 7
// speedup vs baseline: 1.0035x; 1.0035x over previous
#include <cuda_runtime.h>
#include <math.h>
#include <math_constants.h>

#define NPIX 768
#define NB   32
#define PATCH 128
#define NT   64          // 8x8 patches per image
#define TM   128         // matmul tile
#define KC   8           // matmul k-chunk
#define RS   8           // corr_rigid row-stripe

// ---------------- scratch (static device globals; no runtime alloc) -------
__device__ float  g_cr[NB][121];              // rigid corr window (SIGNED partial sums)
__device__ float  g_S[NB];                    // checkerboard sum per image
__device__ float  g_rsh[NB][2];               // rigid shifts (shx, shy)
__device__ float  g_hr[NB][2][NPIX];          // REAL fractional-shift kernels
__device__ float  g_sig[NB];                  // sin(pi s1) sin(pi s2) / N^2
__device__ float  g_ur[(size_t)NB*NPIX*NPIX]; // pass1 result (real)
__device__ float  g_pncc[NB*NT][121];         // patch ncc windows (abs)
__device__ float  g_sx[NB*NT];                // shift_img_x flattened
__device__ float  g_sy[NB*NT];                // shift_img_y flattened

// ---------------- helpers -------------------------------------------------
__device__ __forceinline__ float lgclip(const float* ncc, int a, int b) {
    a = a < 0 ? 0 : (a > 10 ? 10 : a);
    b = b < 0 ? 0 : (b > 10 ? 10 : b);
    return logf(ncc[a * 11 + b] + 1e-8f);
}

__device__ __forceinline__ void subpixel11(const float* ncc, float lbx, float lby,
                                           float* oshx, float* oshy) {
    int am = 0; float best = ncc[0];
    #pragma unroll 1
    for (int i = 1; i < 121; i++) { if (ncc[i] > best) { best = ncc[i]; am = i; } }
    int sx = am / 11, sy = am % 11;
    float lxm = lgclip(ncc, sx - 1, sy);
    float lxp = lgclip(ncc, sx + 1, sy);
    float lym = lgclip(ncc, sx, sy - 1);
    float lyp = lgclip(ncc, sx, sy + 1);
    float l0  = 4.0f * lgclip(ncc, sx, sy);
    *oshx = -((float)sx + lbx) - (lxm - lxp) / (2.0f * lxm - l0 + 2.0f * lxp);
    *oshy = -((float)sy + lby) - (lym - lyp) / (2.0f * lym - l0 + 2.0f * lyp);
}

// ---------------- stage 0: zero accumulators ------------------------------
__global__ void init_zero() {
    int i = blockIdx.x * 256 + threadIdx.x;
    if (i < NB * 121) ((float*)g_cr)[i] = 0.f;
    if (i < NB) g_S[i] = 0.f;
}

// ---------------- stage 0b: checkerboard sum S_b = sum (-1)^{m+n} D ------
__global__ void sum_sign(const float* __restrict__ data) {
    int b = blockIdx.y;
    const float* D = data + (size_t)b * NPIX * NPIX;
    float acc = 0.f;
    for (int i = blockIdx.x * 256 + threadIdx.x; i < NPIX * NPIX; i += gridDim.x * 256) {
        float v = D[i];
        // NPIX even -> n parity == i parity; sign = (-1)^{m+n}
        int par = ((i / NPIX) + i) & 1;
        acc += par ? -v : v;
    }
    acc += __shfl_down_sync(0xffffffffu, acc, 16);
    acc += __shfl_down_sync(0xffffffffu, acc, 8);
    acc += __shfl_down_sync(0xffffffffu, acc, 4);
    acc += __shfl_down_sync(0xffffffffu, acc, 2);
    acc += __shfl_down_sync(0xffffffffu, acc, 1);
    __shared__ float sw[8];
    int lane = threadIdx.x & 31, wrp = threadIdx.x >> 5;
    if (lane == 0) sw[wrp] = acc;
    __syncthreads();
    if (threadIdx.x == 0) {
        float s = 0.f;
        #pragma unroll
        for (int w = 0; w < 8; w++) s += sw[w];
        atomicAdd(&g_S[b], s);
    }
}

// ---------------- stage A: rigid correlation (row-stripe blocks) ----------
// c[a,b] = sum_{x,y} data[x,y] * tpl[(x-a)%N, (y-b)%N],  a,b in [-5,5]
__global__ __launch_bounds__(256) void corr_rigid(const float* __restrict__ data,
                                                  const float* __restrict__ tpl) {
    extern __shared__ float sm2[];
    float* sdat = sm2;                 // RS * NPIX
    float* stpl = sm2 + RS * NPIX;     // (RS+10) * NPIX
    int b = blockIdx.y, X0 = blockIdx.x * RS;
    int tid = threadIdx.x;
    const float* D = data + (size_t)b * NPIX * NPIX + (size_t)X0 * NPIX;

    for (int i = tid; i < RS * NPIX / 4; i += 256)
        ((float4*)sdat)[i] = ((const float4*)D)[i];
    for (int i = tid; i < (RS + 10) * NPIX / 4; i += 256) {
        int r = i / (NPIX / 4), c4 = i % (NPIX / 4);
        int gr = X0 - 5 + r;
        if (gr < 0) gr += NPIX; else if (gr >= NPIX) gr -= NPIX;
        ((float4*)stpl)[i] = ((const float4*)(tpl + (size_t)gr * NPIX))[c4];
    }
    __syncthreads();

    __shared__ float swr[8][11];
    int lane = tid & 31, wrp = tid >> 5;
    for (int wi = 0; wi < 11; wi++) {
        float acc[11];
        #pragma unroll
        for (int j = 0; j < 11; j++) acc[j] = 0.f;
        #pragma unroll 1
        for (int g = 0; g < 6; g++) {
            int gid = tid + g * 256;          // 0..1535 = 8 rows * 192 groups
            int x = gid / 192;
            int y0 = (gid % 192) * 4;
            float4 p4 = *(const float4*)&sdat[x * NPIX + y0];
            const float* rp = stpl + (x + 10 - wi) * NPIX;
            int ysc = y0 - 5;  if (ysc < 0) ysc += NPIX;
            int ym  = y0 - 4;  if (ym  < 0) ym  += NPIX;
            int yp1 = y0 + 4;  if (yp1 >= NPIX) yp1 -= NPIX;
            int yp2 = y0 + 8;  if (yp2 >= NPIX) yp2 -= NPIX;
            float4 Bq = *(const float4*)&rp[ym];
            float4 Cq = *(const float4*)&rp[y0];
            float4 Dq = *(const float4*)&rp[yp1];
            float tv[14] = { rp[ysc], Bq.x, Bq.y, Bq.z, Bq.w,
                             Cq.x, Cq.y, Cq.z, Cq.w, Dq.x, Dq.y, Dq.z, Dq.w, rp[yp2] };
            float pv[4] = { p4.x, p4.y, p4.z, p4.w };
            #pragma unroll
            for (int wj = 0; wj < 11; wj++)
                #pragma unroll
                for (int yo = 0; yo < 4; yo++)
                    acc[wj] += pv[yo] * tv[yo + 10 - wj];
        }
        #pragma unroll
        for (int j = 0; j < 11; j++) {
            float v = acc[j];
            v += __shfl_down_sync(0xffffffffu, v, 16);
            v += __shfl_down_sync(0xffffffffu, v, 8);
            v += __shfl_down_sync(0xffffffffu, v, 4);
            v += __shfl_down_sync(0xffffffffu, v, 2);
            v += __shfl_down_sync(0xffffffffu, v, 1);
            if (lane == 0) swr[wrp][j] = v;
        }
        __syncthreads();
        if (tid < 11) {
            float s = 0.f;
            #pragma unroll
            for (int w = 0; w < 8; w++) s += swr[w][tid];
            atomicAdd(&g_cr[b][wi * 11 + tid], s);
        }
        __syncthreads();
    }
}

// ---------------- stage A2: rigid subpixel (fabs of accumulated sums) -----
__global__ void rigid_subpixel(float* __restrict__ out_rs) {
    int b = threadIdx.x;
    if (b >= NB) return;
    float loc[121];
    for (int i = 0; i < 121; i++) loc[i] = fabsf(g_cr[b][i]);
    float shx, shy;
    subpixel11(loc, -5.0f, -5.0f, &shx, &shy);
    g_rsh[b][0] = shx; g_rsh[b][1] = shy;
    out_rs[b * 2 + 0] = shx;
    out_rs[b * 2 + 1] = shy;
}

// ---------------- stage B0: real Dirichlet shift kernels ------------------
__global__ void compute_h() {
    int b = blockIdx.x, axis = blockIdx.y, j = threadIdx.x;
    double s = (double)g_rsh[b][axis];
    double t = (double)j - s;
    double a = CUDART_PI * t / 768.0;
    double S1r, S1i;
    double den = sin(a);
    if (fabs(den) < 1e-12) { S1r = 384.0; S1i = 0.0; }
    else {
        double ratio = sin(384.0 * a) / den;
        double ph = 383.0 * a;
        S1r = ratio * cos(ph); S1i = ratio * sin(ph);
    }
    double ang = 2.0 * CUDART_PI * s + CUDART_PI * t;
    double fr = 1.0 + cos(ang), fi = sin(ang);
    g_hr[b][axis][j] = (float)((S1r * fr - S1i * fi) / 768.0);
    if (j == 0 && axis == 0) {
        double s1 = (double)g_rsh[b][0], s2 = (double)g_rsh[b][1];
        g_sig[b] = (float)(sin(CUDART_PI * s1) * sin(CUDART_PI * s2) / (768.0 * 768.0));
    }
}

// ---------------- stage B1: u = R1 * D (real circulant matmul) ------------
__global__ __launch_bounds__(256) void pass1(const float* __restrict__ data) {
    int x0 = blockIdx.y * TM, y0 = blockIdx.x * TM, b = blockIdx.z;
    const float* D = data + (size_t)b * NPIX * NPIX;
    const float* h = g_hr[b][0];
    __shared__ float sd[KC][TM];
    __shared__ float sh[TM + KC];
    int tx = threadIdx.x, ty = threadIdx.y, tid = ty * 16 + tx;
    float acc[8][8];
    #pragma unroll
    for (int i = 0; i < 8; i++)
        #pragma unroll
        for (int j = 0; j < 8; j++) acc[i][j] = 0.f;

    for (int m0 = 0; m0 < NPIX; m0 += KC) {
        {
            int idx = tid * 4;
            int mm = idx >> 7, yy = idx & 127;
            *(float4*)&sd[mm][yy] = *(const float4*)&D[(size_t)(m0 + mm) * NPIX + y0 + yy];
        }
        if (tid < TM + KC - 1) {
            int hj = x0 - m0 - (KC - 1) + tid;
            if (hj < 0) hj += NPIX; else if (hj >= NPIX) hj -= NPIX;
            sh[tid] = h[hj];
        }
        __syncthreads();
        float tv[15];
        #pragma unroll
        for (int q = 0; q < 15; q++) tv[q] = sh[ty * 8 + q];
        #pragma unroll
        for (int mm = 0; mm < KC; mm++) {
            float dv[8];
            *(float4*)&dv[0] = *(const float4*)&sd[mm][tx * 8];
            *(float4*)&dv[4] = *(const float4*)&sd[mm][tx * 8 + 4];
            #pragma unroll
            for (int i = 0; i < 8; i++) {
                float hv = tv[i + (KC - 1) - mm];
                #pragma unroll
                for (int j = 0; j < 8; j++) acc[i][j] += hv * dv[j];
            }
        }
        __syncthreads();
    }
    float* ur = g_ur + (size_t)b * NPIX * NPIX;
    #pragma unroll
    for (int i = 0; i < 8; i++) {
        int x = x0 + ty * 8 + i;
        *(float4*)&ur[(size_t)x * NPIX + y0 + tx * 8]     = *(float4*)&acc[i][0];
        *(float4*)&ur[(size_t)x * NPIX + y0 + tx * 8 + 4] = *(float4*)&acc[i][4];
    }
}

// ---------------- stage B2: out = u * R2^T - alpha * v v^T ----------------
__global__ __launch_bounds__(256) void pass2(float* __restrict__ out) {
    int x0 = blockIdx.y * TM, y0 = blockIdx.x * TM, b = blockIdx.z;
    const float* u = g_ur + (size_t)b * NPIX * NPIX;
    const float* h = g_hr[b][1];
    __shared__ float su[TM][KC + 1];
    __shared__ float sh[TM + KC];
    int tx = threadIdx.x, ty = threadIdx.y, tid = ty * 16 + tx;
    float acc[8][8];
    #pragma unroll
    for (int i = 0; i < 8; i++)
        #pragma unroll
        for (int j = 0; j < 8; j++) acc[i][j] = 0.f;

    for (int m0 = 0; m0 < NPIX; m0 += KC) {
        {
            int xx = tid >> 1, half = tid & 1;
            float4 v = *(const float4*)&u[(size_t)(x0 + xx) * NPIX + m0 + half * 4];
            su[xx][half * 4 + 0] = v.x; su[xx][half * 4 + 1] = v.y;
            su[xx][half * 4 + 2] = v.z; su[xx][half * 4 + 3] = v.w;
        }
        if (tid < TM + KC - 1) {
            int hj = y0 - m0 - (KC - 1) + tid;
            if (hj < 0) hj += NPIX; else if (hj >= NPIX) hj -= NPIX;
            sh[tid] = h[hj];
        }
        __syncthreads();
        float tv[15];
        #pragma unroll
        for (int q = 0; q < 15; q++) tv[q] = sh[tx * 8 + q];
        #pragma unroll
        for (int mm = 0; mm < KC; mm++) {
            float uv[8];
            #pragma unroll
            for (int i = 0; i < 8; i++) uv[i] = su[ty * 8 + i][mm];
            #pragma unroll
            for (int i = 0; i < 8; i++)
                #pragma unroll
                for (int j = 0; j < 8; j++)
                    acc[i][j] += uv[i] * tv[j + (KC - 1) - mm];
        }
        __syncthreads();
    }
    float alpha = g_sig[b] * g_S[b];
    float* O = out + (size_t)b * NPIX * NPIX;
    #pragma unroll
    for (int i = 0; i < 8; i++) {
        int x = x0 + ty * 8 + i;
        #pragma unroll
        for (int j = 0; j < 8; j++) {
            int y = y0 + tx * 8 + j;
            float corr = ((x + y) & 1) ? -alpha : alpha;   // alpha * (-1)^{x+y}
            acc[i][j] -= corr;
        }
        *(float4*)&O[(size_t)x * NPIX + y0 + tx * 8]     = *(float4*)&acc[i][0];
        *(float4*)&O[(size_t)x * NPIX + y0 + tx * 8 + 4] = *(float4*)&acc[i][4];
    }
}

// ---------------- stage C: patchwise correlation windows ------------------
__global__ __launch_bounds__(256) void patch_corr(const float* __restrict__ data,
                                                  const float* __restrict__ tpl) {
    int p = blockIdx.x;
    int b = p >> 6, t = p & 63;
    int ix = t >> 3, iy = t & 7;
    int xs = (ix < 7) ? 96 * ix : 640;
    int ys = (iy < 7) ? 96 * iy : 640;
    extern __shared__ float sm[];
    float* spat = sm;
    float* stpl = sm + PATCH * PATCH;
    int tid = threadIdx.x;
    const float* D = data + (size_t)b * NPIX * NPIX;

    float rshx = g_rsh[b][0], rshy = g_rsh[b][1];
    int lbx = (int)floorf(-rshx - 5.0f);
    int lby = (int)floorf(-rshy - 5.0f);
    int stx = min(max(64 + lbx, 0), 117);
    int sty = min(max(64 + lby, 0), 117);
    int rot = (54 - sty) & 127;       // pre-rotate template columns

    for (int i = tid; i < PATCH * PATCH; i += 256) {
        int x = i >> 7, y = i & 127;
        spat[i] = D[(size_t)(xs + x) * NPIX + ys + y];
        stpl[i] = tpl[(size_t)(xs + x) * NPIX + ys + ((y + rot) & 127)];
    }
    __syncthreads();

    __shared__ float swr[8][11];
    int lane = tid & 31, wrp = tid >> 5;
    for (int wi = 0; wi < 11; wi++) {
        int a = stx + wi - 64;
        float acc[11];
        #pragma unroll
        for (int j = 0; j < 11; j++) acc[j] = 0.f;
        #pragma unroll 1
        for (int g4 = tid; g4 < 4096; g4 += 256) {
            int x  = g4 >> 5;
            int y0 = (g4 & 31) << 2;
            int txr = ((x - a) + 128) & 127;
            const float* row = stpl + txr * 128;
            const float4 p4 = *reinterpret_cast<const float4*>(spat + x * 128 + y0);
            int y1 = (y0 + 4) & 127, y2 = (y0 + 8) & 127;
            float4 A = *(const float4*)&row[y0];
            float4 Bq = *(const float4*)&row[y1];
            float4 Cq = *(const float4*)&row[y2];
            float tv[14] = { A.x, A.y, A.z, A.w, Bq.x, Bq.y, Bq.z, Bq.w,
                             Cq.x, Cq.y, Cq.z, Cq.w,
                             row[(y0 + 12) & 127], row[(y0 + 13) & 127] };
            float pv[4] = { p4.x, p4.y, p4.z, p4.w };
            #pragma unroll
            for (int wj = 0; wj < 11; wj++)
                #pragma unroll
                for (int yo = 0; yo < 4; yo++)
                    acc[wj] += pv[yo] * tv[yo + 10 - wj];
        }
        #pragma unroll
        for (int wj = 0; wj < 11; wj++) {
            float v = acc[wj];
            v += __shfl_down_sync(0xffffffffu, v, 16);
            v += __shfl_down_sync(0xffffffffu, v, 8);
            v += __shfl_down_sync(0xffffffffu, v, 4);
            v += __shfl_down_sync(0xffffffffu, v, 2);
            v += __shfl_down_sync(0xffffffffu, v, 1);
            if (lane == 0) swr[wrp][wj] = v;
        }
        __syncthreads();
        if (tid < 11) {
            float s = 0.f;
            #pragma unroll
            for (int w = 0; w < 8; w++) s += swr[w][tid];
            g_pncc[p][wi * 11 + tid] = fabsf(s);
        }
        __syncthreads();
    }
}

// ---------------- stage D: patch subpixel ---------------------------------
__global__ void patch_subpixel(float* __restrict__ out_sx, float* __restrict__ out_sy) {
    int p = blockIdx.x * blockDim.x + threadIdx.x;
    if (p >= NB * NT) return;
    int b = p >> 6;
    float rshx = g_rsh[b][0], rshy = g_rsh[b][1];
    float lbx = floorf(-rshx - 5.0f);
    float lby = floorf(-rshy - 5.0f);
    float shx, shy;
    subpixel11(g_pncc[p], lbx, lby, &shx, &shy);
    out_sx[p] = -shx; g_sx[p] = -shx;
    out_sy[p] = -shy; g_sy[p] = -shy;
}

// ---------------- stage E+F: upsample shift fields + warp -----------------
__device__ __forceinline__ float sample0(const float* D, int xi, int yi) {
    bool v = (xi >= 0) & (xi < NPIX) & (yi >= 0) & (yi < NPIX);
    int xc = min(max(xi, 0), NPIX - 1);
    int yc = min(max(yi, 0), NPIX - 1);
    float val = D[yc * NPIX + xc];
    return v ? val : 0.0f;
}

__global__ void warp_pw(const float* __restrict__ data, float* __restrict__ out) {
    int lin = blockIdx.x * 256 + threadIdx.x;
    if (lin >= NPIX * NPIX) return;
    int b = blockIdx.y;
    int X = lin / NPIX, Y = lin % NPIX;
    float fi = (X + 0.5f) * (1.0f / 96.0f) - 0.5f;
    float fj = (Y + 0.5f) * (1.0f / 96.0f) - 0.5f;
    float fi0 = floorf(fi), fj0 = floorf(fj);
    float ti = fi - fi0, tj = fj - fj0;
    int i0 = (int)fi0, j0 = (int)fj0;
    int ia = min(max(i0, 0), 7),     ib = min(max(i0 + 1, 0), 7);
    int ja = min(max(j0, 0), 7),     jb = min(max(j0 + 1, 0), 7);
    const float* sxp = g_sx + b * 64;
    const float* syp = g_sy + b * 64;
    float w00 = (1 - ti) * (1 - tj), w01 = (1 - ti) * tj;
    float w10 = ti * (1 - tj),       w11v = ti * tj;
    float sxv = sxp[ia * 8 + ja] * w00 + sxp[ia * 8 + jb] * w01
              + sxp[ib * 8 + ja] * w10 + sxp[ib * 8 + jb] * w11v;
    float syv = syp[ia * 8 + ja] * w00 + syp[ia * 8 + jb] * w01
              + syp[ib * 8 + ja] * w10 + syp[ib * 8 + jb] * w11v;
    float wx = syv + (float)Y;
    float wy = sxv + (float)X;
    float x0f = floorf(wx), y0f = floorf(wy);
    float dx = wx - x0f, dy = wy - y0f;
    int x0 = (int)x0f, y0 = (int)y0f;
    const float* D = data + (size_t)b * NPIX * NPIX;
    float r = sample0(D, x0, y0)         * (1 - dx) * (1 - dy)
            + sample0(D, x0 + 1, y0)     * dx * (1 - dy)
            + sample0(D, x0, y0 + 1)     * (1 - dx) * dy
            + sample0(D, x0 + 1, y0 + 1) * dx * dy;
    out[(size_t)b * NPIX * NPIX + lin] = r;
}

// ---------------- launch --------------------------------------------------
extern "C" void kernel_launch(void* const* d_in, const int* in_sizes, int n_in,
                              void* d_out, int out_size) {
    const float* data = (const float*)d_in[0];
    const float* tpl  = (const float*)d_in[1];
    if (n_in >= 2 && in_sizes[0] == NPIX * NPIX && in_sizes[1] != NPIX * NPIX) {
        const float* t2 = data; data = tpl; tpl = t2;
    }
    float* out = (float*)d_out;
    const size_t IMG = (size_t)NPIX * NPIX;
    float* out_pw    = out;
    float* out_rigid = out + NB * IMG;
    float* out_rs    = out + 2 * NB * IMG;
    float* out_sx    = out_rs + NB * 2;
    float* out_sy    = out_sx + NB * NT;

    init_zero<<<16, 256>>>();
    sum_sign<<<dim3(32, NB), 256>>>(data);

    int crSmem = (RS + RS + 10) * NPIX * (int)sizeof(float);   // 26*768*4 = 79872
    cudaFuncSetAttribute(corr_rigid, cudaFuncAttributeMaxDynamicSharedMemorySize, crSmem);
    corr_rigid<<<dim3(NPIX / RS, NB), 256, crSmem>>>(data, tpl);

    rigid_subpixel<<<1, 32>>>(out_rs);
    compute_h<<<dim3(NB, 2), NPIX>>>();

    pass1<<<dim3(6, 6, NB), dim3(16, 16)>>>(data);
    pass2<<<dim3(6, 6, NB), dim3(16, 16)>>>(out_rigid);

    int pcSmem = 2 * PATCH * PATCH * (int)sizeof(float);
    cudaFuncSetAttribute(patch_corr, cudaFuncAttributeMaxDynamicSharedMemorySize, pcSmem);
    patch_corr<<<NB * NT, 256, pcSmem>>>(data, tpl);

    patch_subpixel<<<(NB * NT + 255) / 256, 256>>>(out_sx, out_sy);
    warp_pw<<<dim3((NPIX * NPIX + 255) / 256, NB), 256>>>(data, out_pw);
}